// round 15
// baseline (speedup 1.0000x reference)
#include <cuda_runtime.h>
#include <cuda_bf16.h>
#include <stdint.h>
#include <math.h>

#define Hh 160
#define Ww 160
#define Bb 4
#define Cc 64
#define Oo 64
#define NOC 192            // 64 folded pm + 128 qn rows
#define KTOT 576           // k = c*9 + kk (natural order)
#define NTH 320            // 8 consumer warps + 2 producer warps
#define NCW 8
#define TP 32
#define NCHUNK 36          // K chunks of 16

// A tile: k-major, 576 rows x 128B (hi 64B | lo 64B), XOR-swizzled units
#define OFF_A 0
#define A_BYTES (KTOT * 128)               // 73728
// per-consumer-warp B rings: 8 x 2 bufs x (24 rows x 80B)
#define OFF_BR A_BYTES
#define B_ROWB 80
#define B_BUFW (24 * B_ROWB)               // 1920
#define OFF_SCR (OFF_BR + 8 * 2 * B_BUFW)  // 104448: geo(9216) then windows(8960)
#define OFF_MB  (OFF_SCR + 9216)           // 113664: 64 mbarriers
#define SMEM_BYTES (OFF_MB + 512)          // 114176

// scratch during A0/A1 lives inside A region (dead before sampling)
#define OFF_SX   0                         // 8192
#define OFF_SOFF 8192                      // 2304

// window: rows h-9..h+10 (20), cols w0i-12..w0i+43 (56 floats)
#define WROWS 20
#define WCOLS 56
#define WCH_BYTES (WROWS * WCOLS * 4)      // 4480

__device__ __align__(16) __nv_bfloat16 g_Whi[NOC * KTOT];
__device__ __align__(16) __nv_bfloat16 g_Wlo[NOC * KTOT];

// ---------------------------------------------------------------------------
__device__ __forceinline__ uint32_t smem_u32(const void* p) {
    uint32_t a;
    asm("{ .reg .u64 t; cvta.to.shared.u64 t, %1; cvt.u32.u64 %0, t; }"
        : "=r"(a) : "l"(p));
    return a;
}
__device__ __forceinline__ void ldsm4(uint32_t* r, uint32_t a) {
    asm volatile("ldmatrix.sync.aligned.m8n8.x4.shared.b16 {%0,%1,%2,%3}, [%4];"
        : "=r"(r[0]), "=r"(r[1]), "=r"(r[2]), "=r"(r[3]) : "r"(a));
}
__device__ __forceinline__ void ldsm4t(uint32_t* r, uint32_t a) {
    asm volatile("ldmatrix.sync.aligned.m8n8.x4.trans.shared.b16 {%0,%1,%2,%3}, [%4];"
        : "=r"(r[0]), "=r"(r[1]), "=r"(r[2]), "=r"(r[3]) : "r"(a));
}
__device__ __forceinline__ void ldsm2(uint32_t* r, uint32_t a) {
    asm volatile("ldmatrix.sync.aligned.m8n8.x2.shared.b16 {%0,%1}, [%2];"
        : "=r"(r[0]), "=r"(r[1]) : "r"(a));
}
__device__ __forceinline__ void mma16816(float* d, const uint32_t* a,
                                         const uint32_t* b) {
    asm volatile("mma.sync.aligned.m16n8k16.row.col.f32.bf16.bf16.f32 "
        "{%0,%1,%2,%3}, {%4,%5,%6,%7}, {%8,%9}, {%0,%1,%2,%3};"
        : "+f"(d[0]), "+f"(d[1]), "+f"(d[2]), "+f"(d[3])
        : "r"(a[0]), "r"(a[1]), "r"(a[2]), "r"(a[3]), "r"(b[0]), "r"(b[1]));
}
#define CP_ASYNC16(dst, src) \
    asm volatile("cp.async.cg.shared.global [%0], [%1], 16;" \
                 :: "r"(dst), "l"(src) : "memory")
#define CP_COMMIT() asm volatile("cp.async.commit_group;" ::: "memory")
#define CP_WAIT1()  asm volatile("cp.async.wait_group 1;" ::: "memory")
#define CP_WAIT0()  asm volatile("cp.async.wait_group 0;" ::: "memory")
#define BAR_PROD()  asm volatile("bar.sync 1, 64;" ::: "memory")
#define MBARRIER_INIT(addr, cnt) \
    asm volatile("mbarrier.init.shared.b64 [%0], %1;" \
                 :: "r"((uint32_t)(addr)), "r"((uint32_t)(cnt)) : "memory")
#define MBARRIER_ARRIVE(addr) \
    asm volatile("mbarrier.arrive.shared.b64 _, [%0];" \
                 :: "r"((uint32_t)(addr)) : "memory")
#define MBAR_WAIT(mbar, parity) do { \
    uint32_t _m = (uint32_t)(mbar); \
    uint32_t _p = (uint32_t)(parity); \
    uint32_t _d; \
    asm volatile("{\n\t.reg .pred p;\n\t" \
        "mbarrier.try_wait.parity.acquire.cta.shared::cta.b64 p, [%1], %2;\n\t" \
        "selp.b32 %0, 1, 0, p;\n\t}" : "=r"(_d) : "r"(_m), "r"(_p) : "memory"); \
    if (!_d) { \
        asm volatile("{\n\t.reg .pred P1;\n\t" \
            "WL_%=:\n\t" \
            "mbarrier.try_wait.parity.acquire.cta.shared::cta.b64 P1, [%0], %1, 0x989680;\n\t" \
            "@P1 bra.uni WD_%=;\n\t" \
            "bra.uni WL_%=;\n\t" \
            "WD_%=:\n\t}" :: "r"(_m), "r"(_p) : "memory"); \
    } \
} while (0)

// ---------------------------------------------------------------------------
// prep: fold + bf16-split weights, layout [n][k] row-major, k natural
// ---------------------------------------------------------------------------
__global__ void prep_kernel(const float* __restrict__ w_m,
                            const float* __restrict__ w_n) {
    int idx = blockIdx.x * blockDim.x + threadIdx.x;
    if (idx >= NOC * KTOT) return;
    int n = idx / KTOT;
    int k = idx - n * KTOT;
    float v;
    if (n < 64) v = w_m[n * KTOT + k] + w_m[(n + 64) * KTOT + k];
    else        v = w_n[(n - 64) * KTOT + k];
    __nv_bfloat16 h = __float2bfloat16(v);
    g_Whi[idx] = h;
    g_Wlo[idx] = __float2bfloat16(v - __bfloat162float(h));
}

// ---------------------------------------------------------------------------
// fused kernel: one CTA = 32 px x 192 output rows; warp-specialized overlap
// ---------------------------------------------------------------------------
__global__ void __launch_bounds__(NTH, 2)
pala_mma_kernel(const float* __restrict__ x,
                const float* __restrict__ off_w,
                const float* __restrict__ off_b,
                const float* __restrict__ w0v,
                float* __restrict__ out) {
    extern __shared__ char sm[];
    const uint32_t sb = smem_u32(sm);
    const int tid = threadIdx.x, wid = tid >> 5, lane = tid & 31;
    const int w0i = blockIdx.x * TP;
    const int h = blockIdx.y;
    const int b = blockIdx.z;
    const float* xb = x + (size_t)b * (Cc * Hh * Ww);

    // mbarriers: one per channel, arrive count = 64 (both producer warps)
    if (tid == 0) {
        #pragma unroll 4
        for (int i = 0; i < Cc; i++) MBARRIER_INIT(sb + OFF_MB + 8 * i, 64);
    }

    // --- Phase A0: stage x column tile [64c][32px] ---
    float* s_x = (float*)(sm + OFF_SX);
    for (int i = tid; i < Cc * TP; i += NTH) {
        int c = i >> 5, p = i & 31;
        s_x[i] = xb[(c * Hh + h) * Ww + w0i + p];
    }
    __syncthreads();

    // --- Phase A1: offset 1x1 conv + clip + tanh soft limit ---
    float* s_off = (float*)(sm + OFF_SOFF);      // [2][9][32]
    for (int i = tid; i < 18 * TP; i += NTH) {
        int o = i >> 5, p = i & 31;
        float acc = off_b[o];
        const float* wr = off_w + o * Cc;
        #pragma unroll 8
        for (int c = 0; c < Cc; c++) acc += wr[c] * s_x[c * TP + p];
        float lo, hi;
        if ((o & 1) == 0) { lo = -(float)h; hi = (float)(Hh - h); }
        else              { int gx = w0i + p; lo = -(float)gx; hi = (float)(Ww - gx); }
        float v = fminf(fmaxf(acc, lo), hi);
        if (fabsf(v) >= 8.0f) v = 8.0f * tanhf(v * 0.125f);
        s_off[(o & 1) * 288 + (o >> 1) * TP + p] = v;
    }
    __syncthreads();

    // --- Phase A2: bilinear geometry, window-relative ---
    int*   gI = (int*)(sm + OFF_SCR);
    float* gF = (float*)(sm + OFF_SCR);
    for (int i = tid; i < 288; i += NTH) {
        int kk = i >> 5, p = i & 31;
        float oy = s_off[i];
        float ox = s_off[288 + i];
        float py = (float)(h - 1 + kk / 3) + oy;
        float px = (float)(w0i + p - 1 + kk % 3) + ox;
        float y0f = floorf(py), x0f = floorf(px);
        float wy = py - y0f, wx = px - x0f;
        int y0 = (int)y0f, x0 = (int)x0f;
        int y1 = y0 + 1, x1 = x0 + 1;
        float vy0 = (y0 >= 0 && y0 < Hh) ? 1.f : 0.f;
        float vy1 = (y1 >= 0 && y1 < Hh) ? 1.f : 0.f;
        float vx0 = (x0 >= 0 && x0 < Ww) ? 1.f : 0.f;
        float vx1 = (x1 >= 0 && x1 < Ww) ? 1.f : 0.f;
        int wy0 = min(max(y0 - (h - 9), 0), WROWS - 1);
        int wy1 = min(max(y1 - (h - 9), 0), WROWS - 1);
        int wx0 = min(max(x0 - (w0i - 12), 0), WCOLS - 1);
        int wx1 = min(max(x1 - (w0i - 12), 0), WCOLS - 1);
        gI[0 * 288 + i] = wy0 * WCOLS + wx0;
        gI[1 * 288 + i] = wy0 * WCOLS + wx1;
        gI[2 * 288 + i] = wy1 * WCOLS + wx0;
        gI[3 * 288 + i] = wy1 * WCOLS + wx1;
        gF[4 * 288 + i] = (1.f - wy) * (1.f - wx) * vy0 * vx0;
        gF[5 * 288 + i] = (1.f - wy) * wx         * vy0 * vx1;
        gF[6 * 288 + i] = wy * (1.f - wx)         * vy1 * vx0;
        gF[7 * 288 + i] = wy * wx                 * vy1 * vx1;
    }
    __syncthreads();   // geometry visible; s_x/s_off dead (A region free for STS)

    if (wid < NCW) {
        // ================= CONSUMERS: warp-MMA GEMM over 36 k-chunks ========
        const int n0 = wid * 24;
        const int grp = lane >> 3;
        const int ro = (lane >> 4) * 8 + (lane & 7);   // k-row within 16
        const int swz = lane & 7;                      // == ro & 7
        const uint32_t aBase = sb + OFF_A + (uint32_t)(ro * 128);
        const uint32_t uH0 = (uint32_t)(((0 + ((lane >> 3) & 1)) ^ swz) * 16);
        const uint32_t uH1 = (uint32_t)(((2 + ((lane >> 3) & 1)) ^ swz) * 16);
        const uint32_t uL0 = (uint32_t)(((4 + ((lane >> 3) & 1)) ^ swz) * 16);
        const uint32_t uL1 = (uint32_t)(((6 + ((lane >> 3) & 1)) ^ swz) * 16);
        const int b4off = ((grp >> 1) * 8 + (lane & 7)) * B_ROWB + (grp & 1) * 16;
        const int l16 = lane & 15;
        const int b2off = (16 + (l16 & 7)) * B_ROWB + (l16 >> 3) * 16;
        const uint32_t warpB = sb + OFF_BR + (uint32_t)wid * (2 * B_BUFW);

        #define CP_CHUNK(ck, buf) do { \
            _Pragma("unroll") \
            for (int u = 0; u < 3; u++) { \
                int i = lane + 32 * u; \
                int nl = i >> 2, q = i & 3, half = q >> 1, qq = q & 1; \
                const __nv_bfloat16* src = (half ? g_Wlo : g_Whi) \
                    + (n0 + nl) * KTOT + (ck) * 16 + qq * 8; \
                uint32_t dst = warpB + (buf) * B_BUFW + nl * B_ROWB \
                             + half * 32 + qq * 16; \
                CP_ASYNC16(dst, src); \
            } \
            CP_COMMIT(); \
        } while (0)

        float acc[2][3][4];
        #pragma unroll
        for (int mt = 0; mt < 2; mt++)
            #pragma unroll
            for (int j = 0; j < 3; j++)
                #pragma unroll
                for (int q = 0; q < 4; q++) acc[mt][j][q] = 0.f;

        CP_CHUNK(0, 0);
        CP_CHUNK(1, 1);

        int cReady = -1;
        for (int ck = 0; ck < NCHUNK; ck++) {
            int cLast = (16 * ck + 15) / 9;
            if (cLast > cReady) {
                MBAR_WAIT(sb + OFF_MB + 8 * cLast, 0);
                cReady = cLast;
            }
            if (ck == NCHUNK - 1) { CP_WAIT0(); } else { CP_WAIT1(); }
            __syncwarp();
            const uint32_t bufB = warpB + (uint32_t)(ck & 1) * B_BUFW;
            const uint32_t aCk = aBase + (uint32_t)(ck * 2048);

            uint32_t af[2][2][4];
            ldsm4t(af[0][0], aCk + uH0);
            ldsm4t(af[0][1], aCk + uL0);
            ldsm4t(af[1][0], aCk + uH1);
            ldsm4t(af[1][1], aCk + uL1);
            uint32_t b01[2][4], b2[2][2];
            #pragma unroll
            for (int hl = 0; hl < 2; hl++) {
                ldsm4(b01[hl], bufB + b4off + hl * 32);
                ldsm2(b2[hl],  bufB + b2off + hl * 32);
            }
            #pragma unroll
            for (int mt = 0; mt < 2; mt++) {
                #pragma unroll
                for (int j = 0; j < 3; j++) {
                    const uint32_t* bh = (j < 2) ? &b01[0][j * 2] : b2[0];
                    const uint32_t* bl = (j < 2) ? &b01[1][j * 2] : b2[1];
                    mma16816(acc[mt][j], af[mt][0], bh);   // hi*hi
                    mma16816(acc[mt][j], af[mt][1], bh);   // lo*hi
                    mma16816(acc[mt][j], af[mt][0], bl);   // hi*lo
                }
            }
            if (ck < NCHUNK - 2) CP_CHUNK(ck + 2, ck & 1);
        }
        __syncthreads();   // converge with producers; A reads done

        // --- stage accumulators to smem res[n][m], stride 33 floats (A area) ---
        float* res = (float*)(sm + OFF_A);
        {
            const int g = lane >> 2, tig = lane & 3;
            #pragma unroll
            for (int mt = 0; mt < 2; mt++) {
                #pragma unroll
                for (int j = 0; j < 3; j++) {
                    int nb = n0 + j * 8 + tig * 2;
                    int mb = mt * 16 + g;
                    res[nb * 33 + mb]           = acc[mt][j][0];
                    res[(nb + 1) * 33 + mb]     = acc[mt][j][1];
                    res[nb * 33 + mb + 8]       = acc[mt][j][2];
                    res[(nb + 1) * 33 + mb + 8] = acc[mt][j][3];
                }
            }
        }
        #undef CP_CHUNK
    } else {
        // ================= PRODUCERS: window load + sampling stream =========
        const int pw = wid - NCW;          // 0 or 1
        const int ptid = tid - NCW * 32;   // 0..63
        const int nR = pw ? 4 : 5;

        // cache geometry for owned kk rows in registers
        int kks[5], gi0[5], gi1[5], gi2[5], gi3[5];
        float gf0[5], gf1[5], gf2[5], gf3[5];
        #pragma unroll
        for (int j = 0; j < 5; j++) {
            if (j < nR) {
                int kk = pw ? (5 + j) : j;
                kks[j] = kk;
                int i = kk * TP + lane;
                gi0[j] = gI[i];            gi1[j] = gI[288 + i];
                gi2[j] = gI[2 * 288 + i];  gi3[j] = gI[3 * 288 + i];
                gf0[j] = gF[4 * 288 + i];  gf1[j] = gF[5 * 288 + i];
                gf2[j] = gF[6 * 288 + i];  gf3[j] = gF[7 * 288 + i];
            }
        }
        BAR_PROD();   // both producer warps done reading geo before windows overwrite

        #define WIN_LOAD(c, buf) do { \
            uint32_t wdst_ = sb + OFF_SCR + (uint32_t)(buf) * WCH_BYTES; \
            const float* xc_ = xb + (c) * (Hh * Ww); \
            for (int j_ = ptid; j_ < 280; j_ += 64) { \
                int wr_ = j_ / 14, c4_ = j_ - wr_ * 14; \
                int gy_ = min(max(h - 9 + wr_, 0), Hh - 1); \
                int gx_ = min(max(w0i - 12 + c4_ * 4, 0), Ww - 4); \
                CP_ASYNC16(wdst_ + (uint32_t)(wr_ * WCOLS + c4_ * 4) * 4, \
                           xc_ + gy_ * Ww + gx_); \
            } \
            CP_COMMIT(); \
        } while (0)

        WIN_LOAD(0, 0);
        WIN_LOAD(1, 1);
        for (int c = 0; c < Cc; c++) {
            if (c == Cc - 1) { CP_WAIT0(); } else { CP_WAIT1(); }
            BAR_PROD();   // window c complete across both producer warps
            const float* wb = (const float*)(sm + OFF_SCR
                                             + (uint32_t)(c & 1) * WCH_BYTES);
            #pragma unroll
            for (int j = 0; j < 5; j++) {
                if (j < nR) {
                    float v = gf0[j] * wb[gi0[j]] + gf1[j] * wb[gi1[j]]
                            + gf2[j] * wb[gi2[j]] + gf3[j] * wb[gi3[j]];
                    __nv_bfloat16 hbf = __float2bfloat16(v);
                    __nv_bfloat16 lbf = __float2bfloat16(v - __bfloat162float(hbf));
                    int t = c * 9 + kks[j];
                    char* rp = sm + OFF_A + t * 128 + 2 * (lane & 7);
                    *(__nv_bfloat16*)(rp + ((((lane >> 3)) ^ (t & 7)) << 4)) = hbf;
                    *(__nv_bfloat16*)(rp + (((4 + (lane >> 3)) ^ (t & 7)) << 4)) = lbf;
                }
            }
            MBARRIER_ARRIVE(sb + OFF_MB + 8 * c);   // release: STS visible
            BAR_PROD();   // all reads of window buf done before refill
            if (c + 2 < Cc) WIN_LOAD(c + 2, c & 1);
        }
        #undef WIN_LOAD
        __syncthreads();   // converge with consumers
    }
    __syncthreads();       // res staged, visible to all

    // --- epilogue: (pm + w0) / (1 + |qa| + |qb|) ---
    float* res = (float*)(sm + OFF_A);
    for (int i = tid; i < Oo * TP; i += NTH) {
        int c = i >> 5, p = i & 31;
        float pm = res[c * 33 + p] + __ldg(w0v + c);
        float den = 1.0f + fabsf(res[(64 + c) * 33 + p])
                         + fabsf(res[(128 + c) * 33 + p]);
        out[(((size_t)b * Oo + c) * Hh + h) * Ww + w0i + p] = pm / den;
    }
}

// ---------------------------------------------------------------------------
extern "C" void kernel_launch(void* const* d_in, const int* in_sizes, int n_in,
                              void* d_out, int out_size) {
    (void)in_sizes; (void)n_in; (void)out_size;
    const float* x     = (const float*)d_in[0];
    const float* off_w = (const float*)d_in[1];
    const float* off_b = (const float*)d_in[2];
    const float* w_m   = (const float*)d_in[3];
    const float* w_n   = (const float*)d_in[4];
    const float* w0    = (const float*)d_in[5];
    float* out = (float*)d_out;

    prep_kernel<<<(NOC * KTOT + 255) / 256, 256>>>(w_m, w_n);

    cudaFuncSetAttribute(pala_mma_kernel,
                         cudaFuncAttributeMaxDynamicSharedMemorySize, SMEM_BYTES);
    dim3 grid(Ww / TP, Hh, Bb);
    pala_mma_kernel<<<grid, NTH, SMEM_BYTES>>>(x, off_w, off_b, w0, out);
}